// round 1
// baseline (speedup 1.0000x reference)
#include <cuda_runtime.h>
#include <cstdint>

// Problem constants (fixed by the reference)
#define NN 100000
#define EE 1600000
#define FIN 128
#define HID 64
#define NCLS 16

// Scratch (allocation-free rule: __device__ globals)
__device__ __align__(16) float g_deg[NN];          // deg, then dinv in-place
__device__ __align__(16) float g_norm[EE];
__device__ __align__(16) float g_h[(size_t)NN * HID];
__device__ __align__(16) float g_agg[(size_t)NN * HID];
__device__ __align__(16) float g_x1[(size_t)NN * HID];

static inline int cdiv(long long a, int b) { return (int)((a + b - 1) / b); }

// ---------------------------------------------------------------------------
// Degree / normalization precompute
// ---------------------------------------------------------------------------
__global__ void k_init_deg() {
    int i = blockIdx.x * blockDim.x + threadIdx.x;
    if (i < NN) g_deg[i] = 1.0f;   // implicit self-loop
}

__global__ void k_count_deg(const int* __restrict__ ei) {
    int e = blockIdx.x * blockDim.x + threadIdx.x;
    if (e < EE) atomicAdd(&g_deg[ei[EE + e]], 1.0f);
}

__global__ void k_dinv() {
    int i = blockIdx.x * blockDim.x + threadIdx.x;
    if (i < NN) g_deg[i] = rsqrtf(g_deg[i]);   // g_deg now holds dinv
}

__global__ void k_norm(const int* __restrict__ ei) {
    int e = blockIdx.x * blockDim.x + threadIdx.x;
    if (e < EE) g_norm[e] = g_deg[ei[e]] * g_deg[ei[EE + e]];
}

// ---------------------------------------------------------------------------
// GEMM: h = X @ W ; agg = h * dinv^2 (self-loop term fused as agg init)
// One thread per node row; W staged in shared memory (broadcast reads).
// ---------------------------------------------------------------------------
template <int K, int O>
__global__ void k_gemm(const float* __restrict__ X, const float* __restrict__ W) {
    __shared__ float Ws[K * O];
    for (int i = threadIdx.x; i < K * O; i += blockDim.x) Ws[i] = W[i];
    __syncthreads();

    int node = blockIdx.x * blockDim.x + threadIdx.x;
    if (node >= NN) return;

    float acc[O];
#pragma unroll
    for (int o = 0; o < O; ++o) acc[o] = 0.0f;

    const float4* xr = reinterpret_cast<const float4*>(X + (size_t)node * K);
    for (int k4 = 0; k4 < K / 4; ++k4) {
        float4 xv = xr[k4];
        const float* wrow = &Ws[k4 * 4 * O];
#pragma unroll
        for (int o = 0; o < O; ++o) {
            float a = acc[o];
            a = fmaf(xv.x, wrow[o],         a);
            a = fmaf(xv.y, wrow[O + o],     a);
            a = fmaf(xv.z, wrow[2 * O + o], a);
            a = fmaf(xv.w, wrow[3 * O + o], a);
            acc[o] = a;
        }
    }

    float di = g_deg[node];
    float s = di * di;
    float4* hp = reinterpret_cast<float4*>(&g_h[(size_t)node * O]);
    float4* ap = reinterpret_cast<float4*>(&g_agg[(size_t)node * O]);
#pragma unroll
    for (int o4 = 0; o4 < O / 4; ++o4) {
        float4 v = make_float4(acc[4 * o4], acc[4 * o4 + 1], acc[4 * o4 + 2], acc[4 * o4 + 3]);
        hp[o4] = v;
        ap[o4] = make_float4(v.x * s, v.y * s, v.z * s, v.w * s);
    }
}

// ---------------------------------------------------------------------------
// Scatter: agg[dst] += h[src] * norm[e]
// O/4 threads per edge, each owning one float4 slice; vectorized red.add.
// ---------------------------------------------------------------------------
template <int O>
__global__ void k_scatter(const int* __restrict__ ei) {
    constexpr int G = O / 4;
    int idx = blockIdx.x * blockDim.x + threadIdx.x;
    int e = idx / G;
    if (e >= EE) return;
    int g = idx - e * G;

    int s = ei[e];
    int d = ei[EE + e];
    float w = g_norm[e];

    float4 v = *reinterpret_cast<const float4*>(&g_h[(size_t)s * O + 4 * g]);
    float* p = &g_agg[(size_t)d * O + 4 * g];
    asm volatile("red.global.v4.f32.add [%0], {%1, %2, %3, %4};"
                 :: "l"(p), "f"(v.x * w), "f"(v.y * w), "f"(v.z * w), "f"(v.w * w)
                 : "memory");
}

// ---------------------------------------------------------------------------
// Finalize: out = (relu?)(agg + b)
// ---------------------------------------------------------------------------
template <int O, bool RELU>
__global__ void k_final(const float* __restrict__ b, float* __restrict__ out) {
    int idx = blockIdx.x * blockDim.x + threadIdx.x;
    if (idx >= NN * O) return;
    float v = g_agg[idx] + __ldg(&b[idx & (O - 1)]);
    if (RELU) v = fmaxf(v, 0.0f);
    out[idx] = v;
}

// ---------------------------------------------------------------------------
// Launch
// ---------------------------------------------------------------------------
extern "C" void kernel_launch(void* const* d_in, const int* in_sizes, int n_in,
                              void* d_out, int out_size) {
    const float* x  = (const float*)d_in[0];
    const int*   ei = (const int*)  d_in[1];
    const float* W1 = (const float*)d_in[2];
    const float* b1 = (const float*)d_in[3];
    const float* Wh = (const float*)d_in[4];
    const float* bh = (const float*)d_in[5];
    const float* W2 = (const float*)d_in[6];
    const float* b2 = (const float*)d_in[7];

    float* logits = (float*)d_out;                       // [N, 16]
    float* latent = (float*)d_out + (size_t)NN * NCLS;   // [N, 64]

    float* x1;
    cudaGetSymbolAddress((void**)&x1, g_x1);

    const int T = 256;

    // normalization precompute
    k_init_deg<<<cdiv(NN, T), T>>>();
    k_count_deg<<<cdiv(EE, T), T>>>(ei);
    k_dinv<<<cdiv(NN, T), T>>>();
    k_norm<<<cdiv(EE, T), T>>>(ei);

    // layer 1: x[128] -> 64, relu
    k_gemm<FIN, HID><<<cdiv(NN, 128), 128>>>(x, W1);
    k_scatter<HID><<<cdiv((long long)EE * (HID / 4), T), T>>>(ei);
    k_final<HID, true><<<cdiv((long long)NN * HID, T), T>>>(b1, x1);

    // layer 2: 64 -> 64, relu -> latent (second half of d_out)
    k_gemm<HID, HID><<<cdiv(NN, 128), 128>>>(x1, Wh);
    k_scatter<HID><<<cdiv((long long)EE * (HID / 4), T), T>>>(ei);
    k_final<HID, true><<<cdiv((long long)NN * HID, T), T>>>(bh, latent);

    // layer 3: 64 -> 16, logits (first part of d_out)
    k_gemm<HID, NCLS><<<cdiv(NN, 128), 128>>>(latent, W2);
    k_scatter<NCLS><<<cdiv((long long)EE * (NCLS / 4), T), T>>>(ei);
    k_final<NCLS, false><<<cdiv((long long)NN * NCLS, T), T>>>(b2, logits);
}

// round 2
// speedup vs baseline: 1.2179x; 1.2179x over previous
#include <cuda_runtime.h>
#include <cstdint>

#define NN 100000
#define EE 1600000
#define FIN 128
#define HID 64
#define NCLS 16

#define SCAN_B 512
#define SCAN_NB ((NN + SCAN_B - 1) / SCAN_B)   // 196

// ---- scratch (__device__ globals: allocation-free rule) ----
__device__ __align__(16) int   g_cnt[NN];
__device__ __align__(16) int   g_rowptr[NN + 1];
__device__ __align__(16) int   g_cursor[NN];
__device__ __align__(16) int   g_bsum[SCAN_NB];
__device__ __align__(16) float g_dinv[NN];
__device__ __align__(16) int   g_csr_src[EE];
__device__ __align__(16) float g_csr_w[EE];
__device__ __align__(16) float g_h[(size_t)NN * HID];
__device__ __align__(16) float g_x1[(size_t)NN * HID];

static inline int cdiv(long long a, int b) { return (int)((a + b - 1) / b); }

// ---------------------------------------------------------------------------
// CSR build: histogram -> exclusive scan -> fill
// ---------------------------------------------------------------------------
__global__ void k_zero_cnt() {
    int i = blockIdx.x * blockDim.x + threadIdx.x;
    if (i < NN) g_cnt[i] = 0;
}

__global__ void k_hist(const int* __restrict__ ei) {
    int e = blockIdx.x * blockDim.x + threadIdx.x;
    if (e < EE) atomicAdd(&g_cnt[ei[EE + e]], 1);
}

__global__ void k_scan1() {
    __shared__ int sh[SCAN_B];
    int i = blockIdx.x * SCAN_B + threadIdx.x;
    int v = (i < NN) ? g_cnt[i] : 0;
    sh[threadIdx.x] = v;
    __syncthreads();
    for (int ofs = 1; ofs < SCAN_B; ofs <<= 1) {
        int t = (threadIdx.x >= ofs) ? sh[threadIdx.x - ofs] : 0;
        __syncthreads();
        sh[threadIdx.x] += t;
        __syncthreads();
    }
    if (i < NN) g_rowptr[i] = sh[threadIdx.x] - v;   // exclusive
    if (threadIdx.x == SCAN_B - 1) g_bsum[blockIdx.x] = sh[SCAN_B - 1];
}

__global__ void k_scan2() {
    __shared__ int sh[256];
    int t = threadIdx.x;
    int v = (t < SCAN_NB) ? g_bsum[t] : 0;
    sh[t] = v;
    __syncthreads();
    for (int ofs = 1; ofs < 256; ofs <<= 1) {
        int u = (t >= ofs) ? sh[t - ofs] : 0;
        __syncthreads();
        sh[t] += u;
        __syncthreads();
    }
    if (t < SCAN_NB) g_bsum[t] = sh[t] - v;          // exclusive
}

__global__ void k_scan3() {
    int i = blockIdx.x * blockDim.x + threadIdx.x;
    if (i >= NN) return;
    int rp = g_rowptr[i] + g_bsum[i / SCAN_B];
    g_rowptr[i] = rp;
    g_cursor[i] = rp;
    g_dinv[i] = rsqrtf(1.0f + (float)g_cnt[i]);      // deg + self-loop
    if (i == 0) g_rowptr[NN] = EE;
}

__global__ void k_fill(const int* __restrict__ ei) {
    int e = blockIdx.x * blockDim.x + threadIdx.x;
    if (e >= EE) return;
    int s = ei[e];
    int d = ei[EE + e];
    int pos = atomicAdd(&g_cursor[d], 1);
    g_csr_src[pos] = s;
    g_csr_w[pos] = g_dinv[s] * g_dinv[d];
}

// ---------------------------------------------------------------------------
// GEMM: g_h = X @ W. One thread per node, float4 W reads (broadcast LDS.128).
// ---------------------------------------------------------------------------
template <int K, int O>
__global__ void k_gemm(const float* __restrict__ X, const float* __restrict__ W) {
    __shared__ __align__(16) float Ws[K * O];
    for (int i = threadIdx.x; i < K * O; i += blockDim.x) Ws[i] = W[i];
    __syncthreads();

    int node = blockIdx.x * blockDim.x + threadIdx.x;
    if (node >= NN) return;

    float4 acc[O / 4];
#pragma unroll
    for (int o = 0; o < O / 4; ++o) acc[o] = make_float4(0.f, 0.f, 0.f, 0.f);

    const float4* xr = reinterpret_cast<const float4*>(X + (size_t)node * K);
    for (int k4 = 0; k4 < K / 4; ++k4) {
        float4 xv = xr[k4];
        float xk[4] = {xv.x, xv.y, xv.z, xv.w};
#pragma unroll
        for (int kk = 0; kk < 4; ++kk) {
            const float4* wr = reinterpret_cast<const float4*>(&Ws[(k4 * 4 + kk) * O]);
#pragma unroll
            for (int o = 0; o < O / 4; ++o) {
                float4 w = wr[o];
                acc[o].x = fmaf(xk[kk], w.x, acc[o].x);
                acc[o].y = fmaf(xk[kk], w.y, acc[o].y);
                acc[o].z = fmaf(xk[kk], w.z, acc[o].z);
                acc[o].w = fmaf(xk[kk], w.w, acc[o].w);
            }
        }
    }

    float4* hp = reinterpret_cast<float4*>(&g_h[(size_t)node * O]);
#pragma unroll
    for (int o = 0; o < O / 4; ++o) hp[o] = acc[o];
}

// ---------------------------------------------------------------------------
// Gather (O=64): one warp per node, float2 per lane.
// out[n] = sum_{e in row(n)} h[src_e]*w_e + h[n]*dinv[n]^2 + b ; optional relu
// ---------------------------------------------------------------------------
template <bool RELU>
__global__ void k_gather64(const float* __restrict__ b, float* __restrict__ out) {
    int node = blockIdx.x * (blockDim.x >> 5) + (threadIdx.x >> 5);
    if (node >= NN) return;
    int lane = threadIdx.x & 31;

    int beg = g_rowptr[node];
    int end = g_rowptr[node + 1];

    float2 acc = make_float2(0.f, 0.f);
    for (int base = beg; base < end; base += 32) {
        int cnt = end - base;
        if (cnt > 32) cnt = 32;
        int   s = 0;
        float w = 0.f;
        if (lane < cnt) {
            s = g_csr_src[base + lane];
            w = g_csr_w[base + lane];
        }
#pragma unroll 8
        for (int j = 0; j < cnt; ++j) {
            int   sj = __shfl_sync(0xffffffffu, s, j);
            float wj = __shfl_sync(0xffffffffu, w, j);
            float2 hv = *reinterpret_cast<const float2*>(&g_h[(size_t)sj * HID + 2 * lane]);
            acc.x = fmaf(hv.x, wj, acc.x);
            acc.y = fmaf(hv.y, wj, acc.y);
        }
    }

    float di = g_dinv[node];
    float s2 = di * di;
    float2 hv = *reinterpret_cast<const float2*>(&g_h[(size_t)node * HID + 2 * lane]);
    acc.x = fmaf(hv.x, s2, acc.x) + b[2 * lane];
    acc.y = fmaf(hv.y, s2, acc.y) + b[2 * lane + 1];
    if (RELU) {
        acc.x = fmaxf(acc.x, 0.f);
        acc.y = fmaxf(acc.y, 0.f);
    }
    *reinterpret_cast<float2*>(&out[(size_t)node * HID + 2 * lane]) = acc;
}

// ---------------------------------------------------------------------------
// Gather (O=16): 16-lane group per node (2 nodes/warp). NN*16 is a multiple of
// 256 so every warp has both halves valid (full-mask shfl is safe).
// ---------------------------------------------------------------------------
template <bool RELU>
__global__ void k_gather16(const float* __restrict__ b, float* __restrict__ out) {
    int gid = (blockIdx.x * blockDim.x + threadIdx.x) >> 4;
    if (gid >= NN) return;
    int lane = threadIdx.x & 15;

    int beg = g_rowptr[gid];
    int end = g_rowptr[gid + 1];

    float acc = 0.f;
    for (int base = beg; base < end; base += 16) {
        int cnt = end - base;
        if (cnt > 16) cnt = 16;
        int   s = 0;
        float w = 0.f;
        if (lane < cnt) {
            s = g_csr_src[base + lane];
            w = g_csr_w[base + lane];
        }
#pragma unroll 8
        for (int j = 0; j < cnt; ++j) {
            int   sj = __shfl_sync(0xffffffffu, s, j, 16);
            float wj = __shfl_sync(0xffffffffu, w, j, 16);
            acc = fmaf(g_h[(size_t)sj * NCLS + lane], wj, acc);
        }
    }

    float di = g_dinv[gid];
    acc = fmaf(g_h[(size_t)gid * NCLS + lane], di * di, acc) + b[lane];
    if (RELU) acc = fmaxf(acc, 0.f);
    out[(size_t)gid * NCLS + lane] = acc;
}

// ---------------------------------------------------------------------------
// Launch
// ---------------------------------------------------------------------------
extern "C" void kernel_launch(void* const* d_in, const int* in_sizes, int n_in,
                              void* d_out, int out_size) {
    const float* x  = (const float*)d_in[0];
    const int*   ei = (const int*)  d_in[1];
    const float* W1 = (const float*)d_in[2];
    const float* b1 = (const float*)d_in[3];
    const float* Wh = (const float*)d_in[4];
    const float* bh = (const float*)d_in[5];
    const float* W2 = (const float*)d_in[6];
    const float* b2 = (const float*)d_in[7];

    float* logits = (float*)d_out;                       // [N, 16]
    float* latent = (float*)d_out + (size_t)NN * NCLS;   // [N, 64]

    float* x1;
    cudaGetSymbolAddress((void**)&x1, g_x1);

    const int T = 256;

    // CSR build
    k_zero_cnt<<<cdiv(NN, T), T>>>();
    k_hist<<<cdiv(EE, T), T>>>(ei);
    k_scan1<<<SCAN_NB, SCAN_B>>>();
    k_scan2<<<1, 256>>>();
    k_scan3<<<cdiv(NN, T), T>>>();
    k_fill<<<cdiv(EE, T), T>>>(ei);

    // layer 1: 128 -> 64, relu
    k_gemm<FIN, HID><<<cdiv(NN, 128), 128>>>(x, W1);
    k_gather64<true><<<cdiv(NN, 8), 256>>>(b1, x1);

    // layer 2: 64 -> 64, relu -> latent
    k_gemm<HID, HID><<<cdiv(NN, 128), 128>>>(x1, Wh);
    k_gather64<true><<<cdiv(NN, 8), 256>>>(bh, latent);

    // layer 3: 64 -> 16, logits
    k_gemm<HID, NCLS><<<cdiv(NN, 128), 128>>>(latent, W2);
    k_gather16<false><<<cdiv((long long)NN * NCLS, T), T>>>(b2, logits);
}

// round 3
// speedup vs baseline: 1.4830x; 1.2177x over previous
#include <cuda_runtime.h>
#include <cstdint>

#define NN 100000
#define EE 1600000
#define FIN 128
#define HID 64
#define NCLS 16

#define SCAN_B 512
#define SCAN_NB ((NN + SCAN_B - 1) / SCAN_B)   // 196

// ---- scratch (__device__ globals: allocation-free rule) ----
__device__ __align__(16) int   g_cnt[NN];
__device__ __align__(16) int   g_rowptr[NN + 1];
__device__ __align__(16) int   g_cursor[NN];
__device__ __align__(16) int   g_bsum[SCAN_NB];
__device__ __align__(16) float g_dinv[NN];
__device__ __align__(16) int2  g_csr[EE];          // {src, float_bits(w)}
__device__ __align__(16) float g_h[(size_t)NN * HID];
__device__ __align__(16) float g_x1[(size_t)NN * HID];

static inline int cdiv(long long a, int b) { return (int)((a + b - 1) / b); }

// ---------------------------------------------------------------------------
// CSR build: histogram -> exclusive scan -> fill
// ---------------------------------------------------------------------------
__global__ void k_zero_cnt() {
    int i = blockIdx.x * blockDim.x + threadIdx.x;
    if (i < NN) g_cnt[i] = 0;
}

__global__ void k_hist(const int* __restrict__ ei) {
    int e = blockIdx.x * blockDim.x + threadIdx.x;
    if (e < EE) atomicAdd(&g_cnt[ei[EE + e]], 1);
}

__global__ void k_scan1() {
    __shared__ int sh[SCAN_B];
    int i = blockIdx.x * SCAN_B + threadIdx.x;
    int v = (i < NN) ? g_cnt[i] : 0;
    sh[threadIdx.x] = v;
    __syncthreads();
    for (int ofs = 1; ofs < SCAN_B; ofs <<= 1) {
        int t = (threadIdx.x >= ofs) ? sh[threadIdx.x - ofs] : 0;
        __syncthreads();
        sh[threadIdx.x] += t;
        __syncthreads();
    }
    if (i < NN) g_rowptr[i] = sh[threadIdx.x] - v;   // exclusive
    if (threadIdx.x == SCAN_B - 1) g_bsum[blockIdx.x] = sh[SCAN_B - 1];
}

__global__ void k_scan2() {
    __shared__ int sh[256];
    int t = threadIdx.x;
    int v = (t < SCAN_NB) ? g_bsum[t] : 0;
    sh[t] = v;
    __syncthreads();
    for (int ofs = 1; ofs < 256; ofs <<= 1) {
        int u = (t >= ofs) ? sh[t - ofs] : 0;
        __syncthreads();
        sh[t] += u;
        __syncthreads();
    }
    if (t < SCAN_NB) g_bsum[t] = sh[t] - v;          // exclusive
}

__global__ void k_scan3() {
    int i = blockIdx.x * blockDim.x + threadIdx.x;
    if (i >= NN) return;
    int rp = g_rowptr[i] + g_bsum[i / SCAN_B];
    g_rowptr[i] = rp;
    g_cursor[i] = rp;
    g_dinv[i] = rsqrtf(1.0f + (float)g_cnt[i]);      // deg + self-loop
    if (i == 0) g_rowptr[NN] = EE;
}

__global__ void k_fill(const int* __restrict__ ei) {
    int e = blockIdx.x * blockDim.x + threadIdx.x;
    if (e >= EE) return;
    int s = ei[e];
    int d = ei[EE + e];
    int pos = atomicAdd(&g_cursor[d], 1);
    g_csr[pos] = make_int2(s, __float_as_int(g_dinv[s] * g_dinv[d]));
}

// ---------------------------------------------------------------------------
// GEMM: g_h = X @ W. One thread per node, float4 smem W reads.
// ---------------------------------------------------------------------------
template <int K, int O>
__global__ void k_gemm(const float* __restrict__ X, const float* __restrict__ W) {
    __shared__ __align__(16) float Ws[K * O];
    for (int i = threadIdx.x; i < K * O; i += blockDim.x) Ws[i] = W[i];
    __syncthreads();

    int node = blockIdx.x * blockDim.x + threadIdx.x;
    if (node >= NN) return;

    float4 acc[O / 4];
#pragma unroll
    for (int o = 0; o < O / 4; ++o) acc[o] = make_float4(0.f, 0.f, 0.f, 0.f);

    const float4* xr = reinterpret_cast<const float4*>(X + (size_t)node * K);
    for (int k4 = 0; k4 < K / 4; ++k4) {
        float4 xv = xr[k4];
        float xk[4] = {xv.x, xv.y, xv.z, xv.w};
#pragma unroll
        for (int kk = 0; kk < 4; ++kk) {
            const float4* wr = reinterpret_cast<const float4*>(&Ws[(k4 * 4 + kk) * O]);
#pragma unroll
            for (int o = 0; o < O / 4; ++o) {
                float4 w = wr[o];
                acc[o].x = fmaf(xk[kk], w.x, acc[o].x);
                acc[o].y = fmaf(xk[kk], w.y, acc[o].y);
                acc[o].z = fmaf(xk[kk], w.z, acc[o].z);
                acc[o].w = fmaf(xk[kk], w.w, acc[o].w);
            }
        }
    }

    float4* hp = reinterpret_cast<float4*>(&g_h[(size_t)node * O]);
#pragma unroll
    for (int o = 0; o < O / 4; ++o) hp[o] = acc[o];
}

// ---------------------------------------------------------------------------
// Gather (O=64): 2 nodes per warp, 16 lanes x float4 per node.
// Joint max-deg loop (predicated) so the two halves never serialize.
// Uniform int2 CSR loads replace shfl broadcast.
// ---------------------------------------------------------------------------
template <bool RELU>
__global__ void k_gather64(const float* __restrict__ b, float* __restrict__ out) {
    int warp = blockIdx.x * (blockDim.x >> 5) + (threadIdx.x >> 5);
    int half = (threadIdx.x >> 4) & 1;
    int node = warp * 2 + half;          // NN even; grid sized exactly
    int lane = threadIdx.x & 15;

    int beg = g_rowptr[node];
    int cnt = g_rowptr[node + 1] - beg;
    int ocnt = __shfl_xor_sync(0xffffffffu, cnt, 16);
    int maxcnt = cnt > ocnt ? cnt : ocnt;

    float4 acc = make_float4(0.f, 0.f, 0.f, 0.f);
#pragma unroll 2
    for (int k = 0; k < maxcnt; ++k) {
        if (k < cnt) {
            int2 c = __ldg(&g_csr[beg + k]);
            float w = __int_as_float(c.y);
            float4 hv = *reinterpret_cast<const float4*>(&g_h[(size_t)c.x * HID + 4 * lane]);
            acc.x = fmaf(hv.x, w, acc.x);
            acc.y = fmaf(hv.y, w, acc.y);
            acc.z = fmaf(hv.z, w, acc.z);
            acc.w = fmaf(hv.w, w, acc.w);
        }
    }

    float di = g_dinv[node];
    float s2 = di * di;
    float4 hv = *reinterpret_cast<const float4*>(&g_h[(size_t)node * HID + 4 * lane]);
    float4 bv = *reinterpret_cast<const float4*>(&b[4 * lane]);
    acc.x = fmaf(hv.x, s2, acc.x) + bv.x;
    acc.y = fmaf(hv.y, s2, acc.y) + bv.y;
    acc.z = fmaf(hv.z, s2, acc.z) + bv.z;
    acc.w = fmaf(hv.w, s2, acc.w) + bv.w;
    if (RELU) {
        acc.x = fmaxf(acc.x, 0.f);
        acc.y = fmaxf(acc.y, 0.f);
        acc.z = fmaxf(acc.z, 0.f);
        acc.w = fmaxf(acc.w, 0.f);
    }
    *reinterpret_cast<float4*>(&out[(size_t)node * HID + 4 * lane]) = acc;
}

// ---------------------------------------------------------------------------
// Gather (O=16): 2 nodes per warp, 16 lanes x 1 float per node.
// ---------------------------------------------------------------------------
template <bool RELU>
__global__ void k_gather16(const float* __restrict__ b, float* __restrict__ out) {
    int warp = blockIdx.x * (blockDim.x >> 5) + (threadIdx.x >> 5);
    int half = (threadIdx.x >> 4) & 1;
    int node = warp * 2 + half;
    int lane = threadIdx.x & 15;

    int beg = g_rowptr[node];
    int cnt = g_rowptr[node + 1] - beg;
    int ocnt = __shfl_xor_sync(0xffffffffu, cnt, 16);
    int maxcnt = cnt > ocnt ? cnt : ocnt;

    float acc = 0.f;
#pragma unroll 2
    for (int k = 0; k < maxcnt; ++k) {
        if (k < cnt) {
            int2 c = __ldg(&g_csr[beg + k]);
            float w = __int_as_float(c.y);
            acc = fmaf(g_h[(size_t)c.x * NCLS + lane], w, acc);
        }
    }

    float di = g_dinv[node];
    acc = fmaf(g_h[(size_t)node * NCLS + lane], di * di, acc) + __ldg(&b[lane]);
    if (RELU) acc = fmaxf(acc, 0.f);
    out[(size_t)node * NCLS + lane] = acc;
}

// ---------------------------------------------------------------------------
// Launch
// ---------------------------------------------------------------------------
extern "C" void kernel_launch(void* const* d_in, const int* in_sizes, int n_in,
                              void* d_out, int out_size) {
    const float* x  = (const float*)d_in[0];
    const int*   ei = (const int*)  d_in[1];
    const float* W1 = (const float*)d_in[2];
    const float* b1 = (const float*)d_in[3];
    const float* Wh = (const float*)d_in[4];
    const float* bh = (const float*)d_in[5];
    const float* W2 = (const float*)d_in[6];
    const float* b2 = (const float*)d_in[7];

    float* logits = (float*)d_out;                       // [N, 16]
    float* latent = (float*)d_out + (size_t)NN * NCLS;   // [N, 64]

    float* x1;
    cudaGetSymbolAddress((void**)&x1, g_x1);

    const int T = 256;
    const int GB = cdiv(NN, 16);   // 2 nodes/warp, 8 warps/block -> 16 nodes/block

    // CSR build
    k_zero_cnt<<<cdiv(NN, T), T>>>();
    k_hist<<<cdiv(EE, T), T>>>(ei);
    k_scan1<<<SCAN_NB, SCAN_B>>>();
    k_scan2<<<1, 256>>>();
    k_scan3<<<cdiv(NN, T), T>>>();
    k_fill<<<cdiv(EE, T), T>>>(ei);

    // layer 1: 128 -> 64, relu
    k_gemm<FIN, HID><<<cdiv(NN, 128), 128>>>(x, W1);
    k_gather64<true><<<GB, T>>>(b1, x1);

    // layer 2: 64 -> 64, relu -> latent
    k_gemm<HID, HID><<<cdiv(NN, 128), 128>>>(x1, Wh);
    k_gather64<true><<<GB, T>>>(bh, latent);

    // layer 3: 64 -> 16, logits
    k_gemm<HID, NCLS><<<cdiv(NN, 128), 128>>>(latent, W2);
    k_gather16<false><<<GB, T>>>(b2, logits);
}